// round 1
// baseline (speedup 1.0000x reference)
#include <cuda_runtime.h>
#include <math.h>

// Problem constants
#define D_  768
#define H_  12
#define E_  64
#define S_  2000
#define MQ  2048    // B*L*TQ = 4*64*8
#define BLn 256     // B*L
#define TQn 8

// Scratch (device globals: allocation-free)
__device__ float g_Xq[MQ * D_];
__device__ float g_Xk[S_ * D_];
__device__ float g_Xv[S_ * D_];
__device__ float g_Qb[MQ * D_];
__device__ float g_Kb[S_ * D_];
__device__ float g_Vb[S_ * D_];
__device__ float g_Ob[MQ * D_];
__device__ float g_Pool[BLn * D_];

// ---------------------------------------------------------------------------
// LayerNorm: one block per row of 768, 256 threads (3 elems/thread)
// ---------------------------------------------------------------------------
__global__ void ln_kernel(const float* __restrict__ x, float* __restrict__ y,
                          const float* __restrict__ g, const float* __restrict__ b) {
    int row = blockIdx.x;
    const float* xr = x + (size_t)row * D_;
    int t = threadIdx.x;
    float v0 = xr[t];
    float v1 = xr[t + 256];
    float v2 = xr[t + 512];
    float s  = v0 + v1 + v2;
    float ss = v0 * v0 + v1 * v1 + v2 * v2;

    __shared__ float redS[8], redQ[8];
    #pragma unroll
    for (int o = 16; o > 0; o >>= 1) {
        s  += __shfl_xor_sync(0xffffffffu, s, o);
        ss += __shfl_xor_sync(0xffffffffu, ss, o);
    }
    int warp = t >> 5, lane = t & 31;
    if (lane == 0) { redS[warp] = s; redQ[warp] = ss; }
    __syncthreads();
    float sum = 0.f, sq = 0.f;
    #pragma unroll
    for (int w = 0; w < 8; w++) { sum += redS[w]; sq += redQ[w]; }

    float mean = sum * (1.0f / D_);
    float var  = sq * (1.0f / D_) - mean * mean;
    float rs   = rsqrtf(var + 1e-5f);

    float* yr = y + (size_t)row * D_;
    yr[t]       = (v0 - mean) * rs * g[t]       + b[t];
    yr[t + 256] = (v1 - mean) * rs * g[t + 256] + b[t + 256];
    yr[t + 512] = (v2 - mean) * rs * g[t + 512] + b[t + 512];
}

// ---------------------------------------------------------------------------
// SGEMM: C[M][768] = A[M][768] @ W[768][768]^T + bias
// 64x64 tile, BK=16, 256 threads, 4x4 microtile per thread
// grid: (768/64, ceil(M/64))
// ---------------------------------------------------------------------------
__global__ void gemm_bias_kernel(const float* __restrict__ A,
                                 const float* __restrict__ W,
                                 const float* __restrict__ bias,
                                 float* __restrict__ C, int M) {
    __shared__ float As[16][68];   // k-major, padded
    __shared__ float Bs[16][68];

    int t  = threadIdx.x;
    int tx = t & 15, ty = t >> 4;
    int row0 = blockIdx.y * 64;
    int col0 = blockIdx.x * 64;

    float acc[4][4] = {};

    int lm = t >> 2;         // tile row 0..63 for loading
    int lk = (t & 3) << 2;   // 0,4,8,12

    for (int k0 = 0; k0 < D_; k0 += 16) {
        float4 av = make_float4(0.f, 0.f, 0.f, 0.f);
        int ar = row0 + lm;
        if (ar < M) av = *(const float4*)(A + (size_t)ar * D_ + k0 + lk);
        As[lk + 0][lm] = av.x; As[lk + 1][lm] = av.y;
        As[lk + 2][lm] = av.z; As[lk + 3][lm] = av.w;

        float4 bv = *(const float4*)(W + (size_t)(col0 + lm) * D_ + k0 + lk);
        Bs[lk + 0][lm] = bv.x; Bs[lk + 1][lm] = bv.y;
        Bs[lk + 2][lm] = bv.z; Bs[lk + 3][lm] = bv.w;
        __syncthreads();

        #pragma unroll
        for (int k = 0; k < 16; k++) {
            float4 a = *(const float4*)&As[k][ty * 4];
            float4 b = *(const float4*)&Bs[k][tx * 4];
            acc[0][0] += a.x * b.x; acc[0][1] += a.x * b.y; acc[0][2] += a.x * b.z; acc[0][3] += a.x * b.w;
            acc[1][0] += a.y * b.x; acc[1][1] += a.y * b.y; acc[1][2] += a.y * b.z; acc[1][3] += a.y * b.w;
            acc[2][0] += a.z * b.x; acc[2][1] += a.z * b.y; acc[2][2] += a.z * b.z; acc[2][3] += a.z * b.w;
            acc[3][0] += a.w * b.x; acc[3][1] += a.w * b.y; acc[3][2] += a.w * b.z; acc[3][3] += a.w * b.w;
        }
        __syncthreads();
    }

    #pragma unroll
    for (int i = 0; i < 4; i++) {
        int r = row0 + ty * 4 + i;
        if (r < M) {
            #pragma unroll
            for (int j = 0; j < 4; j++) {
                int c = col0 + tx * 4 + j;
                C[(size_t)r * D_ + c] = acc[i][j] + bias[c];
            }
        }
    }
}

// ---------------------------------------------------------------------------
// Flash attention: per block (query tile of 128 rows, head h).
// Online softmax over S=2000 bank entries in chunks of 64.
// grid: (MQ/128, 12), 256 threads, dynamic smem 102400 B
// ---------------------------------------------------------------------------
#define QT 128
#define SC 64
#define ATTN_SMEM ((64 * 132 + 64 * 68 + 64 * 64 + 128 * 68) * 4)

__global__ void attn_kernel(const float* __restrict__ Q, const float* __restrict__ K,
                            const float* __restrict__ V, const int* __restrict__ mask,
                            float* __restrict__ O) {
    extern __shared__ float sm[];
    float* Qs = sm;                    // [64][132]  k-major query tile
    float* Ks = Qs + 64 * 132;         // [64][68]   k-major key chunk
    float* Vs = Ks + 64 * 68;          // [64][64]   [s][e] value chunk
    float* Ps = Vs + 64 * 64;          // [128][68]  probabilities

    int h    = blockIdx.y;
    int row0 = blockIdx.x * QT;
    int t    = threadIdx.x;
    int tx   = t & 15, ty = t >> 4;

    // Load Q tile (k-major)
    for (int idx = t; idx < QT * 64; idx += 256) {
        int r = idx >> 6, e = idx & 63;
        Qs[e * 132 + r] = Q[(size_t)(row0 + r) * D_ + h * 64 + e];
    }

    float m_i[8], l_i[8], acc[8][4];
    #pragma unroll
    for (int i = 0; i < 8; i++) {
        m_i[i] = -1e30f; l_i[i] = 0.f;
        #pragma unroll
        for (int j = 0; j < 4; j++) acc[i][j] = 0.f;
    }

    for (int s0 = 0; s0 < S_; s0 += SC) {
        int scl = min(SC, S_ - s0);
        __syncthreads();   // protect Ks/Vs/Qs from prior-phase readers

        for (int idx = t; idx < SC * 64; idx += 256) {
            int s = idx >> 6, e = idx & 63;
            float kv = 0.f, vv = 0.f;
            if (s < scl) {
                kv = K[(size_t)(s0 + s) * D_ + h * 64 + e];
                vv = V[(size_t)(s0 + s) * D_ + h * 64 + e];
            }
            Ks[e * 68 + s]  = kv;
            Vs[s * 64 + e]  = vv;
        }
        __syncthreads();

        // Scores: 8 rows x 4 cols per thread, dot-64
        float sc[8][4] = {};
        #pragma unroll 16
        for (int k = 0; k < 64; k++) {
            float4 a0 = *(const float4*)&Qs[k * 132 + ty * 8];
            float4 a1 = *(const float4*)&Qs[k * 132 + ty * 8 + 4];
            float4 b  = *(const float4*)&Ks[k * 68 + tx * 4];
            float av[8] = {a0.x, a0.y, a0.z, a0.w, a1.x, a1.y, a1.z, a1.w};
            float bv[4] = {b.x, b.y, b.z, b.w};
            #pragma unroll
            for (int i = 0; i < 8; i++)
                #pragma unroll
                for (int j = 0; j < 4; j++)
                    sc[i][j] += av[i] * bv[j];
        }

        // Mask + scale
        bool ok[4];
        #pragma unroll
        for (int j = 0; j < 4; j++) {
            int sl = tx * 4 + j;
            ok[j] = (sl < scl) && (mask[s0 + sl] != 0);
        }

        // Online softmax per row (row spread over a 16-lane half-warp)
        #pragma unroll
        for (int i = 0; i < 8; i++) {
            float mx = -1e30f;
            #pragma unroll
            for (int j = 0; j < 4; j++) {
                sc[i][j] = ok[j] ? sc[i][j] * 0.125f : -1e30f;
                mx = fmaxf(mx, sc[i][j]);
            }
            #pragma unroll
            for (int o = 1; o < 16; o <<= 1)
                mx = fmaxf(mx, __shfl_xor_sync(0xffffffffu, mx, o));
            float mn   = fmaxf(m_i[i], mx);
            float corr = __expf(m_i[i] - mn);
            m_i[i] = mn;
            float p0 = __expf(sc[i][0] - mn);
            float p1 = __expf(sc[i][1] - mn);
            float p2 = __expf(sc[i][2] - mn);
            float p3 = __expf(sc[i][3] - mn);
            *(float4*)&Ps[(ty * 8 + i) * 68 + tx * 4] = make_float4(p0, p1, p2, p3);
            float ps = p0 + p1 + p2 + p3;
            #pragma unroll
            for (int o = 1; o < 16; o <<= 1)
                ps += __shfl_xor_sync(0xffffffffu, ps, o);
            l_i[i] = l_i[i] * corr + ps;
            #pragma unroll
            for (int j = 0; j < 4; j++) acc[i][j] *= corr;
        }
        __syncthreads();

        // acc += P @ V
        #pragma unroll 8
        for (int s = 0; s < SC; s++) {
            float4 v = *(const float4*)&Vs[s * 64 + tx * 4];
            #pragma unroll
            for (int i = 0; i < 8; i++) {
                float p = Ps[(ty * 8 + i) * 68 + s];
                acc[i][0] += p * v.x;
                acc[i][1] += p * v.y;
                acc[i][2] += p * v.z;
                acc[i][3] += p * v.w;
            }
        }
    }

    #pragma unroll
    for (int i = 0; i < 8; i++) {
        float inv = 1.0f / l_i[i];
        int r = row0 + ty * 8 + i;
        #pragma unroll
        for (int j = 0; j < 4; j++)
            O[(size_t)r * D_ + h * 64 + tx * 4 + j] = acc[i][j] * inv;
    }
}

// ---------------------------------------------------------------------------
// Mean-pool over TQ=8: (2048,768) -> (256,768)
// ---------------------------------------------------------------------------
__global__ void pool_kernel(const float* __restrict__ O, float* __restrict__ P) {
    int idx = blockIdx.x * 256 + threadIdx.x;
    if (idx >= BLn * D_) return;
    int bl = idx / D_, d = idx % D_;
    float s = 0.f;
    #pragma unroll
    for (int tq = 0; tq < TQn; tq++)
        s += O[(size_t)(bl * TQn + tq) * D_ + d];
    P[idx] = s * (1.0f / TQn);
}

// ---------------------------------------------------------------------------
extern "C" void kernel_launch(void* const* d_in, const int* in_sizes, int n_in,
                              void* d_out, int out_size) {
    const float* target     = (const float*)d_in[0];
    const float* key_bank   = (const float*)d_in[1];
    const float* value_bank = (const float*)d_in[2];
    const int*   bank_mask  = (const int*)  d_in[3];
    const float* Wq = (const float*)d_in[4];
    const float* bq = (const float*)d_in[5];
    const float* Wk = (const float*)d_in[6];
    const float* bk = (const float*)d_in[7];
    const float* Wv = (const float*)d_in[8];
    const float* bv = (const float*)d_in[9];
    const float* Wo = (const float*)d_in[10];
    const float* bo = (const float*)d_in[11];
    const float* gq = (const float*)d_in[12];
    const float* betaq = (const float*)d_in[13];
    const float* gkv = (const float*)d_in[14];
    const float* betakv = (const float*)d_in[15];
    float* out = (float*)d_out;

    float *Xq, *Xk, *Xv, *Qb, *Kb, *Vb, *Ob, *Pool;
    cudaGetSymbolAddress((void**)&Xq,  g_Xq);
    cudaGetSymbolAddress((void**)&Xk,  g_Xk);
    cudaGetSymbolAddress((void**)&Xv,  g_Xv);
    cudaGetSymbolAddress((void**)&Qb,  g_Qb);
    cudaGetSymbolAddress((void**)&Kb,  g_Kb);
    cudaGetSymbolAddress((void**)&Vb,  g_Vb);
    cudaGetSymbolAddress((void**)&Ob,  g_Ob);
    cudaGetSymbolAddress((void**)&Pool, g_Pool);

    cudaFuncSetAttribute(attn_kernel,
                         cudaFuncAttributeMaxDynamicSharedMemorySize, ATTN_SMEM);

    // 1. LayerNorms
    ln_kernel<<<MQ, 256>>>(target, Xq, gq, betaq);
    ln_kernel<<<S_, 256>>>(key_bank, Xk, gkv, betakv);
    ln_kernel<<<S_, 256>>>(value_bank, Xv, gkv, betakv);

    // 2. Projections
    gemm_bias_kernel<<<dim3(D_ / 64, MQ / 64), 256>>>(Xq, Wq, bq, Qb, MQ);
    gemm_bias_kernel<<<dim3(D_ / 64, (S_ + 63) / 64), 256>>>(Xk, Wk, bk, Kb, S_);
    gemm_bias_kernel<<<dim3(D_ / 64, (S_ + 63) / 64), 256>>>(Xv, Wv, bv, Vb, S_);

    // 3. Attention (flash, online softmax)
    attn_kernel<<<dim3(MQ / QT, H_), 256, ATTN_SMEM>>>(Qb, Kb, Vb, bank_mask, Ob);

    // 4. Mean-pool over TQ
    pool_kernel<<<(BLn * D_ + 255) / 256, 256>>>(Ob, Pool);

    // 5. Output projection -> d_out
    gemm_bias_kernel<<<dim3(D_ / 64, BLn / 64), 256>>>(Pool, Wo, bo, out, BLn);
}

// round 2
// speedup vs baseline: 2.7346x; 2.7346x over previous
#include <cuda_runtime.h>
#include <math.h>

// Problem constants
#define D_  768
#define H_  12
#define E_  64
#define S_  2000
#define MQ  2048    // B*L*TQ
#define BLn 256     // B*L
#define TQn 8

// Scratch (device globals: allocation-free)
__device__ float g_Xq[MQ * D_];
__device__ float g_Xk[S_ * D_];
__device__ float g_Xv[S_ * D_];
__device__ float g_Qb[MQ * D_];
__device__ float g_Kb[S_ * D_];
__device__ float g_Vb[S_ * D_];
__device__ float g_Ob[MQ * D_];
__device__ float g_Pool[BLn * D_];

// ---------------------------------------------------------------------------
// helpers
// ---------------------------------------------------------------------------
__device__ __forceinline__ unsigned f2tf(float x) {
    unsigned r;
    asm("cvt.rna.tf32.f32 %0, %1;" : "=r"(r) : "f"(x));
    return r;
}

__device__ __forceinline__ void mma_tf32(float* d, const unsigned* a,
                                         unsigned b0, unsigned b1) {
    asm volatile(
        "mma.sync.aligned.m16n8k8.row.col.f32.tf32.tf32.f32 "
        "{%0,%1,%2,%3},{%4,%5,%6,%7},{%8,%9},{%0,%1,%2,%3};\n"
        : "+f"(d[0]), "+f"(d[1]), "+f"(d[2]), "+f"(d[3])
        : "r"(a[0]), "r"(a[1]), "r"(a[2]), "r"(a[3]), "r"(b0), "r"(b1));
}

// ---------------------------------------------------------------------------
// LayerNorm: one block per row of 768, 256 threads
// ---------------------------------------------------------------------------
__global__ void ln_kernel(const float* __restrict__ x, float* __restrict__ y,
                          const float* __restrict__ g, const float* __restrict__ b) {
    int row = blockIdx.x;
    const float* xr = x + (size_t)row * D_;
    int t = threadIdx.x;
    float v0 = xr[t], v1 = xr[t + 256], v2 = xr[t + 512];
    float s  = v0 + v1 + v2;
    float ss = v0 * v0 + v1 * v1 + v2 * v2;

    __shared__ float redS[8], redQ[8];
    #pragma unroll
    for (int o = 16; o > 0; o >>= 1) {
        s  += __shfl_xor_sync(0xffffffffu, s, o);
        ss += __shfl_xor_sync(0xffffffffu, ss, o);
    }
    int warp = t >> 5, lane = t & 31;
    if (lane == 0) { redS[warp] = s; redQ[warp] = ss; }
    __syncthreads();
    float sum = 0.f, sq = 0.f;
    #pragma unroll
    for (int w = 0; w < 8; w++) { sum += redS[w]; sq += redQ[w]; }

    float mean = sum * (1.0f / D_);
    float var  = sq * (1.0f / D_) - mean * mean;
    float rs   = rsqrtf(var + 1e-5f);

    float* yr = y + (size_t)row * D_;
    yr[t]       = (v0 - mean) * rs * g[t]       + b[t];
    yr[t + 256] = (v1 - mean) * rs * g[t + 256] + b[t + 256];
    yr[t + 512] = (v2 - mean) * rs * g[t + 512] + b[t + 512];
}

// ---------------------------------------------------------------------------
// Batched TF32 GEMM: C[M][768] = A[M][768] @ W^T + bias
// CTA 128x128 tile, BK=32, 256 threads (8 warps 2x4), warp tile 64x32 (4m x 4n)
// gridDim.z selects one of up to 3 (A,W,bias,C,M) sets.
// ---------------------------------------------------------------------------
__global__ __launch_bounds__(256, 2)
void gemm3_tf32(const float* A0, const float* W0, const float* bi0, float* C0, int M0,
                const float* A1, const float* W1, const float* bi1, float* C1, int M1,
                const float* A2, const float* W2, const float* bi2, float* C2, int M2) {
    const float* A; const float* W; const float* bias; float* C; int M;
    if (blockIdx.z == 0) { A = A0; W = W0; bias = bi0; C = C0; M = M0; }
    else if (blockIdx.z == 1) { A = A1; W = W1; bias = bi1; C = C1; M = M1; }
    else { A = A2; W = W2; bias = bi2; C = C2; M = M2; }

    __shared__ unsigned As[128 * 36];
    __shared__ unsigned Ws[128 * 36];

    int t = threadIdx.x, w = t >> 5, lane = t & 31;
    int g = lane >> 2, c = lane & 3;
    int wm = w >> 2, wn = w & 3;          // wm 0..1, wn 0..3
    int row0 = blockIdx.y * 128;
    int col0 = blockIdx.x * 128;

    float acc[4][4][4];
    #pragma unroll
    for (int i = 0; i < 4; i++)
        #pragma unroll
        for (int j = 0; j < 4; j++)
            #pragma unroll
            for (int k = 0; k < 4; k++) acc[i][j][k] = 0.f;

    for (int k0 = 0; k0 < D_; k0 += 32) {
        __syncthreads();
        #pragma unroll
        for (int i = t; i < 1024; i += 256) {
            int r = i >> 3, kq = (i & 7) << 2;
            int ar = row0 + r;
            float4 av = make_float4(0.f, 0.f, 0.f, 0.f);
            if (ar < M) av = *(const float4*)(A + (size_t)ar * D_ + k0 + kq);
            uint4 ua = make_uint4(f2tf(av.x), f2tf(av.y), f2tf(av.z), f2tf(av.w));
            *(uint4*)&As[r * 36 + kq] = ua;

            float4 wv = *(const float4*)(W + (size_t)(col0 + r) * D_ + k0 + kq);
            uint4 uw = make_uint4(f2tf(wv.x), f2tf(wv.y), f2tf(wv.z), f2tf(wv.w));
            *(uint4*)&Ws[r * 36 + kq] = uw;
        }
        __syncthreads();

        #pragma unroll
        for (int ks = 0; ks < 4; ks++) {
            int kk = ks * 8;
            unsigned a[4][4];
            #pragma unroll
            for (int mt = 0; mt < 4; mt++) {
                int base = wm * 64 + mt * 16;
                a[mt][0] = As[(base + g)     * 36 + kk + c];
                a[mt][1] = As[(base + g + 8) * 36 + kk + c];
                a[mt][2] = As[(base + g)     * 36 + kk + 4 + c];
                a[mt][3] = As[(base + g + 8) * 36 + kk + 4 + c];
            }
            #pragma unroll
            for (int nt = 0; nt < 4; nt++) {
                int n = wn * 32 + nt * 8 + g;
                unsigned b0 = Ws[n * 36 + kk + c];
                unsigned b1 = Ws[n * 36 + kk + 4 + c];
                #pragma unroll
                for (int mt = 0; mt < 4; mt++)
                    mma_tf32(acc[mt][nt], a[mt], b0, b1);
            }
        }
    }

    #pragma unroll
    for (int mt = 0; mt < 4; mt++) {
        int rA = row0 + wm * 64 + mt * 16 + g;
        int rB = rA + 8;
        #pragma unroll
        for (int nt = 0; nt < 4; nt++) {
            int colb = col0 + wn * 32 + nt * 8 + 2 * c;
            float b0v = bias[colb], b1v = bias[colb + 1];
            if (rA < M) {
                C[(size_t)rA * D_ + colb]     = acc[mt][nt][0] + b0v;
                C[(size_t)rA * D_ + colb + 1] = acc[mt][nt][1] + b1v;
            }
            if (rB < M) {
                C[(size_t)rB * D_ + colb]     = acc[mt][nt][2] + b0v;
                C[(size_t)rB * D_ + colb + 1] = acc[mt][nt][3] + b1v;
            }
        }
    }
}

// ---------------------------------------------------------------------------
// TF32 flash attention
// Per CTA: 256 query rows x head h. 8 warps, each warp owns 32 rows (2 m16
// tiles) across the full 64-col bank chunk. SC=64 bank chunk. Online softmax,
// quad-local reductions only.
// grid: (MQ/256, 12), 256 threads
// ---------------------------------------------------------------------------
#define AQT 256
#define ASC 64
// smem words: Qs 256*68 + Ks 64*68 + Vs 64*72 + Ps 256*68 + mask 64
#define ATTN_WORDS (256*68 + 64*68 + 64*72 + 256*68 + 64)
#define ATTN_SMEM  (ATTN_WORDS * 4)

__global__ __launch_bounds__(256, 1)
void attn_tf32(const float* __restrict__ Q, const float* __restrict__ K,
               const float* __restrict__ V, const int* __restrict__ mask,
               float* __restrict__ O) {
    extern __shared__ unsigned smu[];
    unsigned* Qs = smu;                      // [256][68]
    unsigned* Ks = Qs + 256 * 68;            // [64][68]  (s-major [s][e])
    unsigned* Vs = Ks + 64 * 68;             // [64][72]  (s-major [s][e])
    unsigned* Ps = Vs + 64 * 72;             // [256][68]
    float* maskAdd = (float*)(Ps + 256 * 68);// [64]

    int h = blockIdx.y;
    int row0 = blockIdx.x * AQT;
    int t = threadIdx.x, w = t >> 5, lane = t & 31;
    int g = lane >> 2, c = lane & 3;
    int wrow = w * 32;

    // load Q tile (tf32)
    #pragma unroll 4
    for (int i = t; i < AQT * 16; i += 256) {
        int r = i >> 4, e4 = (i & 15) << 2;
        float4 q4 = *(const float4*)(Q + (size_t)(row0 + r) * D_ + h * E_ + e4);
        uint4 u = make_uint4(f2tf(q4.x), f2tf(q4.y), f2tf(q4.z), f2tf(q4.w));
        *(uint4*)&Qs[r * 68 + e4] = u;
    }

    float mA[2] = {-1e30f, -1e30f}, mB[2] = {-1e30f, -1e30f};
    float lA[2] = {0.f, 0.f}, lB[2] = {0.f, 0.f};
    float acc[2][8][4];
    #pragma unroll
    for (int mt = 0; mt < 2; mt++)
        #pragma unroll
        for (int nt = 0; nt < 8; nt++)
            #pragma unroll
            for (int k = 0; k < 4; k++) acc[mt][nt][k] = 0.f;

    const int nChunks = (S_ + ASC - 1) / ASC;   // 32
    for (int ch = 0; ch < nChunks; ch++) {
        int s0 = ch * ASC;
        __syncthreads();

        // stage K, V chunk (tf32), zero-padded tail
        #pragma unroll 4
        for (int i = t; i < ASC * 16; i += 256) {
            int s = i >> 4, e4 = (i & 15) << 2;
            int gs = s0 + s;
            float4 kv = make_float4(0.f, 0.f, 0.f, 0.f);
            float4 vv = make_float4(0.f, 0.f, 0.f, 0.f);
            if (gs < S_) {
                kv = *(const float4*)(K + (size_t)gs * D_ + h * E_ + e4);
                vv = *(const float4*)(V + (size_t)gs * D_ + h * E_ + e4);
            }
            *(uint4*)&Ks[s * 68 + e4] = make_uint4(f2tf(kv.x), f2tf(kv.y), f2tf(kv.z), f2tf(kv.w));
            *(uint4*)&Vs[s * 72 + e4] = make_uint4(f2tf(vv.x), f2tf(vv.y), f2tf(vv.z), f2tf(vv.w));
        }
        if (t < ASC) {
            int gs = s0 + t;
            maskAdd[t] = (gs < S_ && mask[gs] != 0) ? 0.f : -1e30f;
        }
        __syncthreads();

        // ---- scores = Q @ K^T ----
        float sc[2][8][4];
        #pragma unroll
        for (int mt = 0; mt < 2; mt++)
            #pragma unroll
            for (int nt = 0; nt < 8; nt++)
                #pragma unroll
                for (int k = 0; k < 4; k++) sc[mt][nt][k] = 0.f;

        #pragma unroll
        for (int ks = 0; ks < 8; ks++) {
            int k0 = ks * 8;
            unsigned a[2][4];
            #pragma unroll
            for (int mt = 0; mt < 2; mt++) {
                int base = wrow + mt * 16;
                a[mt][0] = Qs[(base + g)     * 68 + k0 + c];
                a[mt][1] = Qs[(base + g + 8) * 68 + k0 + c];
                a[mt][2] = Qs[(base + g)     * 68 + k0 + 4 + c];
                a[mt][3] = Qs[(base + g + 8) * 68 + k0 + 4 + c];
            }
            #pragma unroll
            for (int nt = 0; nt < 8; nt++) {
                int n0 = nt * 8;
                unsigned b0 = Ks[(n0 + g) * 68 + k0 + c];
                unsigned b1 = Ks[(n0 + g) * 68 + k0 + 4 + c];
                mma_tf32(sc[0][nt], a[0], b0, b1);
                mma_tf32(sc[1][nt], a[1], b0, b1);
            }
        }

        // ---- online softmax (per m-tile; rows g and g+8 within quad) ----
        #pragma unroll
        for (int mt = 0; mt < 2; mt++) {
            float mxA = -1e30f, mxB = -1e30f;
            #pragma unroll
            for (int nt = 0; nt < 8; nt++) {
                int j0 = nt * 8 + 2 * c;
                float ma0 = maskAdd[j0], ma1 = maskAdd[j0 + 1];
                sc[mt][nt][0] = sc[mt][nt][0] * 0.125f + ma0;
                sc[mt][nt][1] = sc[mt][nt][1] * 0.125f + ma1;
                sc[mt][nt][2] = sc[mt][nt][2] * 0.125f + ma0;
                sc[mt][nt][3] = sc[mt][nt][3] * 0.125f + ma1;
                mxA = fmaxf(mxA, fmaxf(sc[mt][nt][0], sc[mt][nt][1]));
                mxB = fmaxf(mxB, fmaxf(sc[mt][nt][2], sc[mt][nt][3]));
            }
            mxA = fmaxf(mxA, __shfl_xor_sync(0xffffffffu, mxA, 1));
            mxA = fmaxf(mxA, __shfl_xor_sync(0xffffffffu, mxA, 2));
            mxB = fmaxf(mxB, __shfl_xor_sync(0xffffffffu, mxB, 1));
            mxB = fmaxf(mxB, __shfl_xor_sync(0xffffffffu, mxB, 2));

            float mnA = fmaxf(mA[mt], mxA);
            float mnB = fmaxf(mB[mt], mxB);
            float corrA = __expf(mA[mt] - mnA);
            float corrB = __expf(mB[mt] - mnB);
            mA[mt] = mnA; mB[mt] = mnB;

            int rowA = wrow + mt * 16 + g;
            int rowB = rowA + 8;
            float psA = 0.f, psB = 0.f;
            #pragma unroll
            for (int nt = 0; nt < 8; nt++) {
                float p0 = __expf(sc[mt][nt][0] - mnA);
                float p1 = __expf(sc[mt][nt][1] - mnA);
                float p2 = __expf(sc[mt][nt][2] - mnB);
                float p3 = __expf(sc[mt][nt][3] - mnB);
                psA += p0 + p1; psB += p2 + p3;
                *(uint2*)&Ps[rowA * 68 + nt * 8 + 2 * c] = make_uint2(f2tf(p0), f2tf(p1));
                *(uint2*)&Ps[rowB * 68 + nt * 8 + 2 * c] = make_uint2(f2tf(p2), f2tf(p3));
            }
            psA += __shfl_xor_sync(0xffffffffu, psA, 1);
            psA += __shfl_xor_sync(0xffffffffu, psA, 2);
            psB += __shfl_xor_sync(0xffffffffu, psB, 1);
            psB += __shfl_xor_sync(0xffffffffu, psB, 2);
            lA[mt] = lA[mt] * corrA + psA;
            lB[mt] = lB[mt] * corrB + psB;
            #pragma unroll
            for (int nt = 0; nt < 8; nt++) {
                acc[mt][nt][0] *= corrA; acc[mt][nt][1] *= corrA;
                acc[mt][nt][2] *= corrB; acc[mt][nt][3] *= corrB;
            }
        }
        __syncwarp();   // Ps written by this warp only; warp-local visibility

        // ---- acc += P @ V ----
        #pragma unroll
        for (int ks = 0; ks < 8; ks++) {
            int k0 = ks * 8;
            unsigned a[2][4];
            #pragma unroll
            for (int mt = 0; mt < 2; mt++) {
                int base = wrow + mt * 16;
                a[mt][0] = Ps[(base + g)     * 68 + k0 + c];
                a[mt][1] = Ps[(base + g + 8) * 68 + k0 + c];
                a[mt][2] = Ps[(base + g)     * 68 + k0 + 4 + c];
                a[mt][3] = Ps[(base + g + 8) * 68 + k0 + 4 + c];
            }
            #pragma unroll
            for (int nt = 0; nt < 8; nt++) {
                int e0 = nt * 8;
                unsigned b0 = Vs[(k0 + c)     * 72 + e0 + g];
                unsigned b1 = Vs[(k0 + 4 + c) * 72 + e0 + g];
                mma_tf32(acc[0][nt], a[0], b0, b1);
                mma_tf32(acc[1][nt], a[1], b0, b1);
            }
        }
    }

    // epilogue
    #pragma unroll
    for (int mt = 0; mt < 2; mt++) {
        int rA = row0 + wrow + mt * 16 + g;
        int rB = rA + 8;
        float invA = 1.0f / lA[mt];
        float invB = 1.0f / lB[mt];
        #pragma unroll
        for (int nt = 0; nt < 8; nt++) {
            int col = h * E_ + nt * 8 + 2 * c;
            *(float2*)&O[(size_t)rA * D_ + col] =
                make_float2(acc[mt][nt][0] * invA, acc[mt][nt][1] * invA);
            *(float2*)&O[(size_t)rB * D_ + col] =
                make_float2(acc[mt][nt][2] * invB, acc[mt][nt][3] * invB);
        }
    }
}

// ---------------------------------------------------------------------------
// Mean-pool over TQ=8
// ---------------------------------------------------------------------------
__global__ void pool_kernel(const float* __restrict__ O, float* __restrict__ P) {
    int idx = blockIdx.x * 256 + threadIdx.x;
    if (idx >= BLn * D_) return;
    int bl = idx / D_, d = idx % D_;
    float s = 0.f;
    #pragma unroll
    for (int tq = 0; tq < TQn; tq++)
        s += O[(size_t)(bl * TQn + tq) * D_ + d];
    P[idx] = s * (1.0f / TQn);
}

// ---------------------------------------------------------------------------
extern "C" void kernel_launch(void* const* d_in, const int* in_sizes, int n_in,
                              void* d_out, int out_size) {
    const float* target     = (const float*)d_in[0];
    const float* key_bank   = (const float*)d_in[1];
    const float* value_bank = (const float*)d_in[2];
    const int*   bank_mask  = (const int*)  d_in[3];
    const float* Wq = (const float*)d_in[4];
    const float* bq = (const float*)d_in[5];
    const float* Wk = (const float*)d_in[6];
    const float* bk = (const float*)d_in[7];
    const float* Wv = (const float*)d_in[8];
    const float* bv = (const float*)d_in[9];
    const float* Wo = (const float*)d_in[10];
    const float* bo = (const float*)d_in[11];
    const float* gq = (const float*)d_in[12];
    const float* betaq = (const float*)d_in[13];
    const float* gkv = (const float*)d_in[14];
    const float* betakv = (const float*)d_in[15];
    float* out = (float*)d_out;

    float *Xq, *Xk, *Xv, *Qb, *Kb, *Vb, *Ob, *Pool;
    cudaGetSymbolAddress((void**)&Xq,  g_Xq);
    cudaGetSymbolAddress((void**)&Xk,  g_Xk);
    cudaGetSymbolAddress((void**)&Xv,  g_Xv);
    cudaGetSymbolAddress((void**)&Qb,  g_Qb);
    cudaGetSymbolAddress((void**)&Kb,  g_Kb);
    cudaGetSymbolAddress((void**)&Vb,  g_Vb);
    cudaGetSymbolAddress((void**)&Ob,  g_Ob);
    cudaGetSymbolAddress((void**)&Pool, g_Pool);

    cudaFuncSetAttribute(attn_tf32,
                         cudaFuncAttributeMaxDynamicSharedMemorySize, ATTN_SMEM);

    // 1. LayerNorms
    ln_kernel<<<MQ, 256>>>(target, Xq, gq, betaq);
    ln_kernel<<<S_, 256>>>(key_bank, Xk, gkv, betakv);
    ln_kernel<<<S_, 256>>>(value_bank, Xv, gkv, betakv);

    // 2. Q/K/V projections in one batched launch (288 CTAs = 2/SM wave)
    gemm3_tf32<<<dim3(D_ / 128, 16, 3), 256>>>(
        Xq, Wq, bq, Qb, MQ,
        Xk, Wk, bk, Kb, S_,
        Xv, Wv, bv, Vb, S_);

    // 3. Attention (tf32 mma flash, online softmax)
    attn_tf32<<<dim3(MQ / AQT, H_), 256, ATTN_SMEM>>>(Qb, Kb, Vb, bank_mask, Ob);

    // 4. Mean-pool over TQ
    pool_kernel<<<(BLn * D_ + 255) / 256, 256>>>(Ob, Pool);

    // 5. Output projection
    gemm3_tf32<<<dim3(D_ / 128, 2, 1), 256>>>(
        Pool, Wo, bo, out, BLn,
        Pool, Wo, bo, out, BLn,
        Pool, Wo, bo, out, BLn);
}